// round 15
// baseline (speedup 1.0000x reference)
#include <cuda_runtime.h>
#include <cuda_fp16.h>
#include <cstdint>

#define BATCH 32
#define L 1024
#define HD 1024

// ---------------------------------------------------------------------------
// Scratch (__device__ globals; no runtime allocation)
// ---------------------------------------------------------------------------
__device__ float g_A[(size_t)BATCH * L * L];   // raw logits, 128 MB
__device__ float g_rmax[BATCH * L];
__device__ float g_rinv[BATCH * L];
__device__ float g_cmax[BATCH * L];
__device__ float g_cinv[BATCH * L];

#define NEL ((size_t)BATCH * L * HD)
__device__ __half g_q0[NEL], g_q1[NEL];   // q 2-way fp16 split (natural [q][h])
__device__ __half g_d0[NEL], g_d1[NEL];   // d 2-way fp16 split (natural [dp][h])
__device__ __half g_s[NEL];               // sq^T fp16 copy (natural [q][h])
__device__ __half g_wr[NEL];              // row-softmax weights [q][dp], fp16
__device__ __half g_wc[NEL];              // col-softmax weights [q][dp] NATURAL, fp16

// ---------------------------------------------------------------------------
// Helpers
// ---------------------------------------------------------------------------
__device__ __forceinline__ uint32_t smem_u32(const void* p) {
    uint32_t a;
    asm("{ .reg .u64 t; cvta.to.shared.u64 t, %1; cvt.u32.u64 %0, t; }" : "=r"(a) : "l"(p));
    return a;
}

#define LDSM4(R0, R1, R2, R3, addr)                                             \
    asm volatile("ldmatrix.sync.aligned.m8n8.x4.shared.b16 {%0,%1,%2,%3}, [%4];" \
                 : "=r"(R0), "=r"(R1), "=r"(R2), "=r"(R3) : "r"(addr))
#define LDSM4T(R0, R1, R2, R3, addr)                                                  \
    asm volatile("ldmatrix.sync.aligned.m8n8.x4.trans.shared.b16 {%0,%1,%2,%3}, [%4];" \
                 : "=r"(R0), "=r"(R1), "=r"(R2), "=r"(R3) : "r"(addr))

#define CP_ASYNC16(saddr, gaddr) \
    asm volatile("cp.async.cg.shared.global [%0], [%1], 16;" :: "r"(saddr), "l"(gaddr))
#define CP_COMMIT() asm volatile("cp.async.commit_group;" ::: "memory")

__device__ __forceinline__ void mma16816(float& c0, float& c1, float& c2, float& c3,
                                         uint32_t a0, uint32_t a1, uint32_t a2, uint32_t a3,
                                         uint32_t b0, uint32_t b1) {
    asm volatile(
        "mma.sync.aligned.m16n8k16.row.col.f32.f16.f16.f32 "
        "{%0,%1,%2,%3}, {%4,%5,%6,%7}, {%8,%9}, {%0,%1,%2,%3};"
        : "+f"(c0), "+f"(c1), "+f"(c2), "+f"(c3)
        : "r"(a0), "r"(a1), "r"(a2), "r"(a3), "r"(b0), "r"(b1));
}

// ---------------------------------------------------------------------------
// Conversion kernels
// ---------------------------------------------------------------------------
union HU4 { __half h[4]; uint2 u; };
union HU8 { __half h[8]; uint4 u; };

// fp32 -> 2-way fp16 split for BOTH q and d in one launch (y selects source)
__global__ __launch_bounds__(256) void k_split2h_dual(
    const float4* __restrict__ xq, uint2* __restrict__ q0, uint2* __restrict__ q1,
    const float4* __restrict__ xd, uint2* __restrict__ d0, uint2* __restrict__ d1) {
    size_t i = (size_t)blockIdx.x * 256 + threadIdx.x;
    const float4* x = blockIdx.y ? xd : xq;
    uint2* o0 = blockIdx.y ? d0 : q0;
    uint2* o1 = blockIdx.y ? d1 : q1;
    float4 v = x[i];
    float xs[4] = {v.x, v.y, v.z, v.w};
    HU4 p0, p1;
    #pragma unroll
    for (int c = 0; c < 4; c++) {
        p0.h[c] = __float2half_rn(xs[c]);
        p1.h[c] = __float2half_rn(xs[c] - __half2float(p0.h[c]));
    }
    o0[i] = p0.u;
    o1[i] = p1.u;
}

// Streaming weight generation, 8 elems/thread, 2 q-rows per CTA:
//   wr[q][dp] = exp(A - rmax[q]) * rinv[q]    (0 for dp >= dlen)
//   wc[q][dp] = exp(A - cmax[dp]) * cinv[dp]  (0 for q  >= qlen)
// I/O predicated to the consumed region. grid (L/2, BATCH), 256 threads.
__global__ __launch_bounds__(256) void k_weights(const int* __restrict__ qlen,
                                                 const int* __restrict__ dlen) {
    int b = blockIdx.y;
    int qq = blockIdx.x * 2 + (threadIdx.x >> 7);
    int t = threadIdx.x & 127;
    int dp0 = t * 8;
    int klq = qlen[b], kld = dlen[b];
    int kldr = (kld + 63) & ~63;   // wr cols consumed by K3
    int klqr = (klq + 63) & ~63;   // wc rows consumed by K4/K5
    bool qv = qq < klq;
    float rm = g_rmax[b * L + qq], ri = g_rinv[b * L + qq];
    size_t base = ((size_t)b << 20) + ((size_t)qq << 10);
    float xs[8] = {0.f, 0.f, 0.f, 0.f, 0.f, 0.f, 0.f, 0.f};
    if (qv || dp0 < kld) {   // skip read of K1-skipped garbage corner
        float4 v0 = *(const float4*)(g_A + base + dp0);
        float4 v1 = *(const float4*)(g_A + base + dp0 + 4);
        xs[0] = v0.x; xs[1] = v0.y; xs[2] = v0.z; xs[3] = v0.w;
        xs[4] = v1.x; xs[5] = v1.y; xs[6] = v1.z; xs[7] = v1.w;
    }
    float4 cm0 = *(const float4*)(g_cmax + b * L + dp0);
    float4 cm1 = *(const float4*)(g_cmax + b * L + dp0 + 4);
    float4 ci0 = *(const float4*)(g_cinv + b * L + dp0);
    float4 ci1 = *(const float4*)(g_cinv + b * L + dp0 + 4);
    float cms[8] = {cm0.x, cm0.y, cm0.z, cm0.w, cm1.x, cm1.y, cm1.z, cm1.w};
    float cis[8] = {ci0.x, ci0.y, ci0.z, ci0.w, ci1.x, ci1.y, ci1.z, ci1.w};
    HU8 pr, pc;
    #pragma unroll
    for (int c = 0; c < 8; c++) {
        int dp = dp0 + c;
        float wr = (dp < kld) ? __expf(xs[c] - rm) * ri : 0.f;
        float wc = qv ? __expf(xs[c] - cms[c]) * cis[c] : 0.f;
        pr.h[c] = __float2half_rn(wr);
        pc.h[c] = __float2half_rn(wc);
    }
    size_t oi = (base >> 3) + t;
    if (dp0 < kldr) ((uint4*)g_wr)[oi] = pr.u;
    if (qq < klqr)  ((uint4*)g_wc)[oi] = pc.u;
}

// ---------------------------------------------------------------------------
// Fused softmax statistics: blockIdx.y==0 -> row path (warp-per-row),
// blockIdx.y==1 -> column path (64 cols x 4 q-segments per CTA, x<16 active).
// grid (128, 2, BATCH), 256 threads.
// ---------------------------------------------------------------------------
__global__ __launch_bounds__(256) void k_stats(const int* __restrict__ qlen,
                                               const int* __restrict__ dlen) {
    int b = blockIdx.z;
    if (blockIdx.y == 0) {
        // ---- row stats ----
        int row = blockIdx.x * 8 + (threadIdx.x >> 5);
        int lane = threadIdx.x & 31;
        int kl = dlen[b];
        const float4* Ar = (const float4*)(g_A + ((size_t)b << 20) + ((size_t)row << 10));
        float v[32];
        #pragma unroll
        for (int i = 0; i < 8; i++) {
            if (lane * 4 + i * 128 < kl) {
                float4 t = Ar[lane + i * 32];
                v[i * 4 + 0] = t.x; v[i * 4 + 1] = t.y;
                v[i * 4 + 2] = t.z; v[i * 4 + 3] = t.w;
            } else {
                v[i * 4 + 0] = v[i * 4 + 1] = v[i * 4 + 2] = v[i * 4 + 3] = -1e30f;
            }
        }
        float m = -1e30f;
        #pragma unroll
        for (int i = 0; i < 8; i++)
            #pragma unroll
            for (int c = 0; c < 4; c++) {
                int idx = (lane + i * 32) * 4 + c;
                if (idx >= kl) v[i * 4 + c] = -1e30f;
                m = fmaxf(m, v[i * 4 + c]);
            }
        #pragma unroll
        for (int off = 16; off; off >>= 1) m = fmaxf(m, __shfl_xor_sync(~0u, m, off));
        float s = 0.f;
        #pragma unroll
        for (int i = 0; i < 32; i++) s += __expf(v[i] - m);
        #pragma unroll
        for (int off = 16; off; off >>= 1) s += __shfl_xor_sync(~0u, s, off);
        if (lane == 0) {
            g_rmax[b * L + row] = m;
            g_rinv[b * L + row] = 1.f / s;
        }
    } else {
        // ---- column stats ----
        if (blockIdx.x >= L / 64) return;
        int tid = threadIdx.x;
        int cl = tid & 63;
        int col = blockIdx.x * 64 + cl;
        int seg = tid >> 6;                    // 0..3
        int kl = qlen[b];
        const float* Ab = g_A + ((size_t)b << 20) + col;
        int q0 = seg * 256;
        int q1 = min(q0 + 256, kl);
        float m[4] = {-1e30f, -1e30f, -1e30f, -1e30f}, s[4] = {0.f, 0.f, 0.f, 0.f};
        int q = q0;
        for (; q + 4 <= q1; q += 4) {
            #pragma unroll
            for (int i = 0; i < 4; i++) {
                float v = Ab[(size_t)(q + i) << 10];
                float nm = fmaxf(m[i], v);
                s[i] = s[i] * __expf(m[i] - nm) + __expf(v - nm);
                m[i] = nm;
            }
        }
        for (; q < q1; q++) {
            float v = Ab[(size_t)q << 10];
            float nm = fmaxf(m[0], v);
            s[0] = s[0] * __expf(m[0] - nm) + __expf(v - nm);
            m[0] = nm;
        }
        float M = fmaxf(fmaxf(m[0], m[1]), fmaxf(m[2], m[3]));
        float S = 0.f;
        #pragma unroll
        for (int i = 0; i < 4; i++) S += s[i] * __expf(m[i] - M);

        __shared__ float sm[4][64], ss[4][64];
        sm[seg][cl] = M;
        ss[seg][cl] = S;
        __syncthreads();
        if (seg == 0) {
            float Mt = sm[0][cl], St = ss[0][cl];
            #pragma unroll
            for (int i = 1; i < 4; i++) {
                float Mo = sm[i][cl], So = ss[i][cl];
                float nm = fmaxf(Mt, Mo);
                St = St * __expf(Mt - nm) + So * __expf(Mo - nm);
                Mt = nm;
            }
            g_cmax[b * L + col] = Mt;
            g_cinv[b * L + col] = 1.f / St;
        }
    }
}

// ---------------------------------------------------------------------------
// Split-fp16 HMMA GEMM. Out[m][n] = sum_k A(m,k) * B(n,k).
// TA/TB: 0 = K-major natural -> ldmatrix; 1 = k-row natural -> ldmatrix.trans.
// Block 128x128, warp tile 64x32 (2x4 warps), Kc templated, cp.async pipeline
// with STAGES buffers (always-commit + wait_group(STAGES-2) pattern).
// SKIP: CTA exits when (m0 >= skq[b] && n0 >= skd[b]) -- region never consumed.
// DUALB: two GEMMs in one launch sharing A/klen; blockIdx.x>>3 selects
// (B0 -> Out) vs (B1 -> OutB).
// ---------------------------------------------------------------------------
template <int NTA, int NTB, int NP, int TA, int TB, int EPI16, int KC, int SKIP,
          int DUALB, int STAGES>
__global__ __launch_bounds__(256, 2) void k_mma(
    const __half* __restrict__ A0, const __half* __restrict__ A1,
    const __half* __restrict__ B0, const __half* __restrict__ B1,
    const int* klen_arr, int klen_fixed,
    float* __restrict__ Out, __half* __restrict__ Out16,
    const int* __restrict__ skq, const int* __restrict__ skd,
    float* __restrict__ OutB) {
    extern __shared__ char smem[];
    const uint32_t sbase = smem_u32(smem);
    constexpr int NAT_RB = KC * 2 + 16;
    constexpr int NAT_TB = 128 * NAT_RB;
    constexpr int TRN_TB = KC * 256;
    constexpr int ATB = TA ? TRN_TB : NAT_TB;
    constexpr int BTB = TB ? TRN_TB : NAT_TB;
    constexpr int STAGE = NTA * ATB + NTB * BTB;
    constexpr int CPR = KC / 8;
    constexpr int OPS = KC * 16 / 256;
    constexpr int KSN = KC / 16;

    const int tid = threadIdx.x, lane = tid & 31, wid = tid >> 5;
    const int b = blockIdx.z, m0 = blockIdx.y * 128;
    int nx = blockIdx.x, which = 0;
    if (DUALB) { which = nx >> 3; nx &= 7; }
    const int n0 = nx * 128;

    if (SKIP) {
        if (m0 >= skq[b] && n0 >= skd[b]) return;
    }

    const int kl = klen_arr ? klen_arr[b] : klen_fixed;
    const int ktiles = (kl + KC - 1) / KC;

    const size_t boff = (size_t)b << 20;
    const __half* gpA[NTA];
    const __half* gpB[NTB];
    gpA[0] = A0 + boff + (TA ? (size_t)m0 : (size_t)m0 * L);
    if (NTA == 2) gpA[1] = A1 + boff + (TA ? (size_t)m0 : (size_t)m0 * L);
    const __half* Bsel = (DUALB && which) ? B1 : B0;
    gpB[0] = Bsel + boff + (TB ? (size_t)n0 : (size_t)n0 * L);
    if (NTB == 2) gpB[1] = B1 + boff + (TB ? (size_t)n0 : (size_t)n0 * L);

    constexpr int PA3[3] = {0, 0, 1}, PB3[3] = {0, 1, 0};

    // warp layout: 2 (m) x 4 (n)
    const int warp_m = (wid >> 2) * 64;
    const int warp_n = (wid & 3) * 32;
    const int rowA = warp_m + (lane & 7) + ((lane >> 3) & 1) * 8;
    const int chA = (lane >> 4) & 1;
    const int rowB = warp_n + (lane & 7) + ((lane >> 4) & 1) * 8;
    const int chB = (lane >> 3) & 1;
    const int kArow = (lane & 7) + ((lane >> 4) & 1) * 8;
    const int mA8 = ((lane >> 3) & 1) * 8;
    const int kBrow = (lane & 7) + ((lane >> 3) & 1) * 8;
    const int nB8 = ((lane >> 4) & 1) * 8;
    const int lsw = (lane & 7) << 4;

    float acc[4][4][4] = {};

    auto load_stage = [&](int t, int buf) {
        const int k0 = t * KC;
        uint32_t sb = sbase + buf * STAGE;
        #pragma unroll
        for (int a = 0; a < NTA; a++) {
            uint32_t tb = sb + a * ATB;
            #pragma unroll
            for (int pp = 0; pp < OPS; pp++) {
                int id = tid + pp * 256;
                if (!TA) {
                    int row = id / CPR, ch = id % CPR;
                    CP_ASYNC16(tb + row * NAT_RB + ch * 16,
                               gpA[a] + (size_t)row * L + k0 + ch * 8);
                } else {
                    int kr = id >> 4, ch = id & 15;
                    CP_ASYNC16(tb + kr * 256 + ((ch ^ (kr & 7)) << 4),
                               gpA[a] + (size_t)(k0 + kr) * L + ch * 8);
                }
            }
        }
        sb += NTA * ATB;
        #pragma unroll
        for (int a = 0; a < NTB; a++) {
            uint32_t tb = sb + a * BTB;
            #pragma unroll
            for (int pp = 0; pp < OPS; pp++) {
                int id = tid + pp * 256;
                if (!TB) {
                    int row = id / CPR, ch = id % CPR;
                    CP_ASYNC16(tb + row * NAT_RB + ch * 16,
                               gpB[a] + (size_t)row * L + k0 + ch * 8);
                } else {
                    int kr = id >> 4, ch = id & 15;
                    CP_ASYNC16(tb + kr * 256 + ((ch ^ (kr & 7)) << 4),
                               gpB[a] + (size_t)(k0 + kr) * L + ch * 8);
                }
            }
        }
    };

    // prologue: fill STAGES-1 buffers
    #pragma unroll
    for (int t = 0; t < STAGES - 1; t++) {
        if (t < ktiles) load_stage(t, t);
        CP_COMMIT();
    }

    for (int t = 0; t < ktiles; t++) {
        asm volatile("cp.async.wait_group %0;" :: "n"(STAGES - 2) : "memory");
        __syncthreads();     // stage t visible AND all warps done with buf (t+STAGES-1)%STAGES
        if (t + STAGES - 1 < ktiles) load_stage(t + STAGES - 1, (t + STAGES - 1) % STAGES);
        CP_COMMIT();         // always commit (keeps group accounting exact)

        const uint32_t sb = sbase + (t % STAGES) * STAGE;
        const uint32_t sbB = sb + NTA * ATB;
        #pragma unroll
        for (int ks = 0; ks < KSN; ks++) {
            uint32_t Bf[NTB][8];
            #pragma unroll
            for (int tm = 0; tm < NTB; tm++)
                #pragma unroll
                for (int g2 = 0; g2 < 2; g2++) {
                    if (!TB) {
                        uint32_t a = sbB + tm * BTB + (rowB + g2 * 16) * NAT_RB
                                   + chB * 16 + ks * 32;
                        LDSM4(Bf[tm][g2 * 4 + 0], Bf[tm][g2 * 4 + 1],
                              Bf[tm][g2 * 4 + 2], Bf[tm][g2 * 4 + 3], a);
                    } else {
                        int n_off = warp_n + g2 * 16 + nB8;
                        int kr = ks * 16 + kBrow;
                        uint32_t a = sbB + tm * BTB + kr * 256
                                   + (((n_off >> 3) << 4) ^ lsw);
                        LDSM4T(Bf[tm][g2 * 4 + 0], Bf[tm][g2 * 4 + 1],
                               Bf[tm][g2 * 4 + 2], Bf[tm][g2 * 4 + 3], a);
                    }
                }
            uint32_t Af[16];
            #pragma unroll
            for (int p = 0; p < NP; p++) {
                const int pa = (NP == 3) ? PA3[p] : 0;
                const int pb = (NP == 3) ? PB3[p] : 0;
                const int pap = (p == 0) ? -1 : ((NP == 3) ? PA3[p - 1] : 0);
                if (pa != pap) {
                    #pragma unroll
                    for (int f = 0; f < 4; f++) {
                        if (!TA) {
                            uint32_t a = sb + pa * ATB + (rowA + f * 16) * NAT_RB
                                       + chA * 16 + ks * 32;
                            LDSM4(Af[f * 4 + 0], Af[f * 4 + 1],
                                  Af[f * 4 + 2], Af[f * 4 + 3], a);
                        } else {
                            int m_off = warp_m + f * 16 + mA8;
                            int kr = ks * 16 + kArow;
                            uint32_t a = sb + pa * ATB + kr * 256
                                       + (((m_off >> 3) << 4) ^ lsw);
                            LDSM4T(Af[f * 4 + 0], Af[f * 4 + 1],
                                   Af[f * 4 + 2], Af[f * 4 + 3], a);
                        }
                    }
                }
                #pragma unroll
                for (int f = 0; f < 4; f++)
                    #pragma unroll
                    for (int g = 0; g < 4; g++) {
                        uint32_t b0 = Bf[pb][(g >> 1) * 4 + (g & 1) * 2];
                        uint32_t b1 = Bf[pb][(g >> 1) * 4 + (g & 1) * 2 + 1];
                        mma16816(acc[f][g][0], acc[f][g][1], acc[f][g][2], acc[f][g][3],
                                 Af[f * 4], Af[f * 4 + 1], Af[f * 4 + 2], Af[f * 4 + 3],
                                 b0, b1);
                    }
            }
        }
    }

    float* Ob = ((DUALB && which) ? OutB : Out) + boff;
    #pragma unroll
    for (int f = 0; f < 4; f++)
        #pragma unroll
        for (int g = 0; g < 4; g++) {
            int row = m0 + warp_m + f * 16 + (lane >> 2);
            int col = n0 + warp_n + g * 8 + (lane & 3) * 2;
            *(float2*)(Ob + (size_t)row * L + col) = make_float2(acc[f][g][0], acc[f][g][1]);
            *(float2*)(Ob + (size_t)(row + 8) * L + col) = make_float2(acc[f][g][2], acc[f][g][3]);
            if (EPI16) {
                __half* Oh = Out16 + boff;
                *(__half2*)(Oh + (size_t)row * L + col) =
                    __floats2half2_rn(acc[f][g][0], acc[f][g][1]);
                *(__half2*)(Oh + (size_t)(row + 8) * L + col) =
                    __floats2half2_rn(acc[f][g][2], acc[f][g][3]);
            }
        }
}

// ---------------------------------------------------------------------------
extern "C" void kernel_launch(void* const* d_in, const int* in_sizes, int n_in,
                              void* d_out, int out_size) {
    const float* q = (const float*)d_in[0];
    const float* dmat = (const float*)d_in[1];
    const int* qlen = (const int*)d_in[2];
    const int* dlen = (const int*)d_in[3];

    float* out = (float*)d_out;
    const size_t ten = (size_t)BATCH * L * HD;
    float* out_cd = out;
    float* out_sq = out + ten;
    float* out_sd = out + 2 * ten;

    void *pA, *pq0, *pq1, *pd0, *pd1, *ps, *pwr, *pwc;
    cudaGetSymbolAddress(&pA, g_A);
    cudaGetSymbolAddress(&pq0, g_q0); cudaGetSymbolAddress(&pq1, g_q1);
    cudaGetSymbolAddress(&pd0, g_d0); cudaGetSymbolAddress(&pd1, g_d1);
    cudaGetSymbolAddress(&ps, g_s);
    cudaGetSymbolAddress(&pwr, g_wr); cudaGetSymbolAddress(&pwc, g_wc);

    // K1: Kc=32, 4 natural tiles of 128*80B -> stage 40960, x2 stages = 81920
    const int SMEM_K1 = 2 * 4 * (128 * 80);
    // K3: Kc=64, natural(wr) 18432 + trans(d) 16384 = 34816/stage, x3 = 104448
    const int SMEM_K3 = 3 * (128 * 144 + 64 * 256);
    // K4/5: Kc=64, 2 trans tiles = 32768/stage, x3 = 98304
    const int SMEM_K45 = 3 * 2 * (64 * 256);
    cudaFuncSetAttribute(k_mma<2, 2, 3, 0, 0, 0, 32, 1, 0, 2>,
                         cudaFuncAttributeMaxDynamicSharedMemorySize, SMEM_K1);
    cudaFuncSetAttribute(k_mma<1, 1, 1, 0, 1, 1, 64, 0, 0, 3>,
                         cudaFuncAttributeMaxDynamicSharedMemorySize, SMEM_K3);
    cudaFuncSetAttribute(k_mma<1, 1, 1, 1, 1, 0, 64, 0, 1, 3>,
                         cudaFuncAttributeMaxDynamicSharedMemorySize, SMEM_K45);

    dim3 gg(HD / 128, L / 128, BATCH);
    int nsplit = (int)(NEL / 4 / 256);

    // 1) 2-way fp16 splits of q AND d in one launch
    k_split2h_dual<<<dim3(nsplit, 2), 256>>>(
        (const float4*)q, (uint2*)pq0, (uint2*)pq1,
        (const float4*)dmat, (uint2*)pd0, (uint2*)pd1);

    // 2) K1: A = q @ d^T  (3 fp16 product terms; skip unconsumed masked tiles)
    k_mma<2, 2, 3, 0, 0, 0, 32, 1, 0, 2><<<gg, 256, SMEM_K1>>>(
        (const __half*)pq0, (const __half*)pq1,
        (const __half*)pd0, (const __half*)pd1,
        nullptr, L, (float*)pA, nullptr, qlen, dlen, nullptr);

    // 3) fused row+col softmax stats in one launch
    k_stats<<<dim3(L / 8, 2, BATCH), 256>>>(qlen, dlen);

    // 4) fused streaming weights (wr + wc, 8 elems/thread, predicated I/O)
    k_weights<<<dim3(L / 2, BATCH), 256>>>(qlen, dlen);

    // 5) K3: sq^T = Wr @ d^T  (A natural, B=d trans; epilogue also emits fp16 sq^T)
    k_mma<1, 1, 1, 0, 1, 1, 64, 0, 0, 3><<<gg, 256, SMEM_K3>>>(
        (const __half*)pwr, nullptr, (const __half*)pd0, nullptr,
        dlen, 0, out_sq, (__half*)ps, nullptr, nullptr, nullptr);

    // 6) K4+K5 in ONE launch: A=wc trans, klen=qlen for both;
    //    blockIdx.x<8 -> B=q^T -> sd^T;  blockIdx.x>=8 -> B=sq^T -> cd^T
    k_mma<1, 1, 1, 1, 1, 0, 64, 0, 1, 3><<<dim3(16, 8, 32), 256, SMEM_K45>>>(
        (const __half*)pwc, nullptr, (const __half*)pq0, (const __half*)ps,
        qlen, 0, out_sd, nullptr, nullptr, nullptr, out_cd);
}

// round 17
// speedup vs baseline: 1.0253x; 1.0253x over previous
#include <cuda_runtime.h>
#include <cuda_fp16.h>
#include <cstdint>

#define BATCH 32
#define L 1024
#define HD 1024

// ---------------------------------------------------------------------------
// Scratch (__device__ globals; no runtime allocation)
// ---------------------------------------------------------------------------
__device__ float g_A[(size_t)BATCH * L * L];   // raw logits, 128 MB
__device__ float g_rmax[BATCH * L];
__device__ float g_rinv[BATCH * L];
__device__ float g_cmax[BATCH * L];
__device__ float g_cinv[BATCH * L];

#define NEL ((size_t)BATCH * L * HD)
__device__ __half g_q0[NEL], g_q1[NEL];   // q 2-way fp16 split (natural [q][h])
__device__ __half g_d0[NEL], g_d1[NEL];   // d 2-way fp16 split (natural [dp][h])
__device__ __half g_s[NEL];               // sq^T fp16 copy (natural [q][h])
__device__ __half g_wr[NEL];              // row-softmax weights [q][dp], fp16
__device__ __half g_wc[NEL];              // col-softmax weights [q][dp] NATURAL, fp16

// ---------------------------------------------------------------------------
// Helpers
// ---------------------------------------------------------------------------
__device__ __forceinline__ uint32_t smem_u32(const void* p) {
    uint32_t a;
    asm("{ .reg .u64 t; cvta.to.shared.u64 t, %1; cvt.u32.u64 %0, t; }" : "=r"(a) : "l"(p));
    return a;
}

#define LDSM4(R0, R1, R2, R3, addr)                                             \
    asm volatile("ldmatrix.sync.aligned.m8n8.x4.shared.b16 {%0,%1,%2,%3}, [%4];" \
                 : "=r"(R0), "=r"(R1), "=r"(R2), "=r"(R3) : "r"(addr))
#define LDSM4T(R0, R1, R2, R3, addr)                                                  \
    asm volatile("ldmatrix.sync.aligned.m8n8.x4.trans.shared.b16 {%0,%1,%2,%3}, [%4];" \
                 : "=r"(R0), "=r"(R1), "=r"(R2), "=r"(R3) : "r"(addr))

#define CP_ASYNC16(saddr, gaddr) \
    asm volatile("cp.async.cg.shared.global [%0], [%1], 16;" :: "r"(saddr), "l"(gaddr))
#define CP_COMMIT() asm volatile("cp.async.commit_group;" ::: "memory")
#define CP_WAIT0()  asm volatile("cp.async.wait_group 0;" ::: "memory")

__device__ __forceinline__ void mma16816(float& c0, float& c1, float& c2, float& c3,
                                         uint32_t a0, uint32_t a1, uint32_t a2, uint32_t a3,
                                         uint32_t b0, uint32_t b1) {
    asm volatile(
        "mma.sync.aligned.m16n8k16.row.col.f32.f16.f16.f32 "
        "{%0,%1,%2,%3}, {%4,%5,%6,%7}, {%8,%9}, {%0,%1,%2,%3};"
        : "+f"(c0), "+f"(c1), "+f"(c2), "+f"(c3)
        : "r"(a0), "r"(a1), "r"(a2), "r"(a3), "r"(b0), "r"(b1));
}

// ---------------------------------------------------------------------------
// Conversion kernels
// ---------------------------------------------------------------------------
union HU4 { __half h[4]; uint2 u; };
union HU8 { __half h[8]; uint4 u; };

// fp32 -> 2-way fp16 split for BOTH q and d in one launch (y selects source)
__global__ __launch_bounds__(256) void k_split2h_dual(
    const float4* __restrict__ xq, uint2* __restrict__ q0, uint2* __restrict__ q1,
    const float4* __restrict__ xd, uint2* __restrict__ d0, uint2* __restrict__ d1) {
    size_t i = (size_t)blockIdx.x * 256 + threadIdx.x;
    const float4* x = blockIdx.y ? xd : xq;
    uint2* o0 = blockIdx.y ? d0 : q0;
    uint2* o1 = blockIdx.y ? d1 : q1;
    float4 v = x[i];
    float xs[4] = {v.x, v.y, v.z, v.w};
    HU4 p0, p1;
    #pragma unroll
    for (int c = 0; c < 4; c++) {
        p0.h[c] = __float2half_rn(xs[c]);
        p1.h[c] = __float2half_rn(xs[c] - __half2float(p0.h[c]));
    }
    o0[i] = p0.u;
    o1[i] = p1.u;
}

// Streaming weight generation, 8 elems/thread, 2 q-rows per CTA:
//   wr[q][dp] = exp(A - rmax[q]) * rinv[q]    (0 for dp >= dlen)
//   wc[q][dp] = exp(A - cmax[dp]) * cinv[dp]  (0 for q  >= qlen)
// I/O predicated to the consumed region. grid (L/2, BATCH), 256 threads.
__global__ __launch_bounds__(256) void k_weights(const int* __restrict__ qlen,
                                                 const int* __restrict__ dlen) {
    int b = blockIdx.y;
    int qq = blockIdx.x * 2 + (threadIdx.x >> 7);
    int t = threadIdx.x & 127;
    int dp0 = t * 8;
    int klq = qlen[b], kld = dlen[b];
    int kldr = (kld + 63) & ~63;   // wr cols consumed by K3
    int klqr = (klq + 63) & ~63;   // wc rows consumed by K4/K5
    bool qv = qq < klq;
    float rm = g_rmax[b * L + qq], ri = g_rinv[b * L + qq];
    size_t base = ((size_t)b << 20) + ((size_t)qq << 10);
    float xs[8] = {0.f, 0.f, 0.f, 0.f, 0.f, 0.f, 0.f, 0.f};
    if (qv || dp0 < kld) {   // skip read of K1-skipped garbage corner
        float4 v0 = *(const float4*)(g_A + base + dp0);
        float4 v1 = *(const float4*)(g_A + base + dp0 + 4);
        xs[0] = v0.x; xs[1] = v0.y; xs[2] = v0.z; xs[3] = v0.w;
        xs[4] = v1.x; xs[5] = v1.y; xs[6] = v1.z; xs[7] = v1.w;
    }
    float4 cm0 = *(const float4*)(g_cmax + b * L + dp0);
    float4 cm1 = *(const float4*)(g_cmax + b * L + dp0 + 4);
    float4 ci0 = *(const float4*)(g_cinv + b * L + dp0);
    float4 ci1 = *(const float4*)(g_cinv + b * L + dp0 + 4);
    float cms[8] = {cm0.x, cm0.y, cm0.z, cm0.w, cm1.x, cm1.y, cm1.z, cm1.w};
    float cis[8] = {ci0.x, ci0.y, ci0.z, ci0.w, ci1.x, ci1.y, ci1.z, ci1.w};
    HU8 pr, pc;
    #pragma unroll
    for (int c = 0; c < 8; c++) {
        int dp = dp0 + c;
        float wr = (dp < kld) ? __expf(xs[c] - rm) * ri : 0.f;
        float wc = qv ? __expf(xs[c] - cms[c]) * cis[c] : 0.f;
        pr.h[c] = __float2half_rn(wr);
        pc.h[c] = __float2half_rn(wc);
    }
    size_t oi = (base >> 3) + t;
    if (dp0 < kldr) ((uint4*)g_wr)[oi] = pr.u;
    if (qq < klqr)  ((uint4*)g_wc)[oi] = pc.u;
}

// ---------------------------------------------------------------------------
// Fused softmax statistics: blockIdx.y==0 -> row path (warp-per-row),
// blockIdx.y==1 -> column path (64 cols x 4 q-segments per CTA, x<16 active).
// grid (128, 2, BATCH), 256 threads.
// ---------------------------------------------------------------------------
__global__ __launch_bounds__(256) void k_stats(const int* __restrict__ qlen,
                                               const int* __restrict__ dlen) {
    int b = blockIdx.z;
    if (blockIdx.y == 0) {
        // ---- row stats ----
        int row = blockIdx.x * 8 + (threadIdx.x >> 5);
        int lane = threadIdx.x & 31;
        int kl = dlen[b];
        const float4* Ar = (const float4*)(g_A + ((size_t)b << 20) + ((size_t)row << 10));
        float v[32];
        #pragma unroll
        for (int i = 0; i < 8; i++) {
            if (lane * 4 + i * 128 < kl) {
                float4 t = Ar[lane + i * 32];
                v[i * 4 + 0] = t.x; v[i * 4 + 1] = t.y;
                v[i * 4 + 2] = t.z; v[i * 4 + 3] = t.w;
            } else {
                v[i * 4 + 0] = v[i * 4 + 1] = v[i * 4 + 2] = v[i * 4 + 3] = -1e30f;
            }
        }
        float m = -1e30f;
        #pragma unroll
        for (int i = 0; i < 8; i++)
            #pragma unroll
            for (int c = 0; c < 4; c++) {
                int idx = (lane + i * 32) * 4 + c;
                if (idx >= kl) v[i * 4 + c] = -1e30f;
                m = fmaxf(m, v[i * 4 + c]);
            }
        #pragma unroll
        for (int off = 16; off; off >>= 1) m = fmaxf(m, __shfl_xor_sync(~0u, m, off));
        float s = 0.f;
        #pragma unroll
        for (int i = 0; i < 32; i++) s += __expf(v[i] - m);
        #pragma unroll
        for (int off = 16; off; off >>= 1) s += __shfl_xor_sync(~0u, s, off);
        if (lane == 0) {
            g_rmax[b * L + row] = m;
            g_rinv[b * L + row] = 1.f / s;
        }
    } else {
        // ---- column stats ----
        if (blockIdx.x >= L / 64) return;
        int tid = threadIdx.x;
        int cl = tid & 63;
        int col = blockIdx.x * 64 + cl;
        int seg = tid >> 6;                    // 0..3
        int kl = qlen[b];
        const float* Ab = g_A + ((size_t)b << 20) + col;
        int q0 = seg * 256;
        int q1 = min(q0 + 256, kl);
        float m[4] = {-1e30f, -1e30f, -1e30f, -1e30f}, s[4] = {0.f, 0.f, 0.f, 0.f};
        int q = q0;
        for (; q + 4 <= q1; q += 4) {
            #pragma unroll
            for (int i = 0; i < 4; i++) {
                float v = Ab[(size_t)(q + i) << 10];
                float nm = fmaxf(m[i], v);
                s[i] = s[i] * __expf(m[i] - nm) + __expf(v - nm);
                m[i] = nm;
            }
        }
        for (; q < q1; q++) {
            float v = Ab[(size_t)q << 10];
            float nm = fmaxf(m[0], v);
            s[0] = s[0] * __expf(m[0] - nm) + __expf(v - nm);
            m[0] = nm;
        }
        float M = fmaxf(fmaxf(m[0], m[1]), fmaxf(m[2], m[3]));
        float S = 0.f;
        #pragma unroll
        for (int i = 0; i < 4; i++) S += s[i] * __expf(m[i] - M);

        __shared__ float sm[4][64], ss[4][64];
        sm[seg][cl] = M;
        ss[seg][cl] = S;
        __syncthreads();
        if (seg == 0) {
            float Mt = sm[0][cl], St = ss[0][cl];
            #pragma unroll
            for (int i = 1; i < 4; i++) {
                float Mo = sm[i][cl], So = ss[i][cl];
                float nm = fmaxf(Mt, Mo);
                St = St * __expf(Mt - nm) + So * __expf(Mo - nm);
                Mt = nm;
            }
            g_cmax[b * L + col] = Mt;
            g_cinv[b * L + col] = 1.f / St;
        }
    }
}

// ---------------------------------------------------------------------------
// Split-fp16 HMMA GEMM. Out[m][n] = sum_k A(m,k) * B(n,k).
// TA/TB: 0 = K-major natural -> ldmatrix; 1 = k-row natural -> ldmatrix.trans.
// Block 128x128, warp tile 64x32 (2x4 warps), Kc templated, cp.async x2 buffer.
// SKIP: CTA exits when (m0 >= skq[b] && n0 >= skd[b]) -- region never consumed.
// DUALB: two GEMMs in one launch sharing A/klen; blockIdx.x>>3 selects
// (B0 -> Out) vs (B1 -> OutB).
// ---------------------------------------------------------------------------
template <int NTA, int NTB, int NP, int TA, int TB, int EPI16, int KC, int SKIP, int DUALB>
__global__ __launch_bounds__(256, 2) void k_mma(
    const __half* __restrict__ A0, const __half* __restrict__ A1,
    const __half* __restrict__ B0, const __half* __restrict__ B1,
    const int* klen_arr, int klen_fixed,
    float* __restrict__ Out, __half* __restrict__ Out16,
    const int* __restrict__ skq, const int* __restrict__ skd,
    float* __restrict__ OutB) {
    extern __shared__ char smem[];
    const uint32_t sbase = smem_u32(smem);
    constexpr int NAT_RB = KC * 2 + 16;
    constexpr int NAT_TB = 128 * NAT_RB;
    constexpr int TRN_TB = KC * 256;
    constexpr int ATB = TA ? TRN_TB : NAT_TB;
    constexpr int BTB = TB ? TRN_TB : NAT_TB;
    constexpr int STAGE = NTA * ATB + NTB * BTB;
    constexpr int CPR = KC / 8;
    constexpr int OPS = KC * 16 / 256;
    constexpr int KSN = KC / 16;

    const int tid = threadIdx.x, lane = tid & 31, wid = tid >> 5;
    const int b = blockIdx.z, m0 = blockIdx.y * 128;
    int nx = blockIdx.x, which = 0;
    if (DUALB) { which = nx >> 3; nx &= 7; }
    const int n0 = nx * 128;

    if (SKIP) {
        if (m0 >= skq[b] && n0 >= skd[b]) return;
    }

    const int kl = klen_arr ? klen_arr[b] : klen_fixed;
    const int ktiles = (kl + KC - 1) / KC;

    const size_t boff = (size_t)b << 20;
    const __half* gpA[NTA];
    const __half* gpB[NTB];
    gpA[0] = A0 + boff + (TA ? (size_t)m0 : (size_t)m0 * L);
    if (NTA == 2) gpA[1] = A1 + boff + (TA ? (size_t)m0 : (size_t)m0 * L);
    const __half* Bsel = (DUALB && which) ? B1 : B0;
    gpB[0] = Bsel + boff + (TB ? (size_t)n0 : (size_t)n0 * L);
    if (NTB == 2) gpB[1] = B1 + boff + (TB ? (size_t)n0 : (size_t)n0 * L);

    constexpr int PA3[3] = {0, 0, 1}, PB3[3] = {0, 1, 0};

    // warp layout: 2 (m) x 4 (n)
    const int warp_m = (wid >> 2) * 64;
    const int warp_n = (wid & 3) * 32;
    const int rowA = warp_m + (lane & 7) + ((lane >> 3) & 1) * 8;
    const int chA = (lane >> 4) & 1;
    const int rowB = warp_n + (lane & 7) + ((lane >> 4) & 1) * 8;
    const int chB = (lane >> 3) & 1;
    const int kArow = (lane & 7) + ((lane >> 4) & 1) * 8;
    const int mA8 = ((lane >> 3) & 1) * 8;
    const int kBrow = (lane & 7) + ((lane >> 3) & 1) * 8;
    const int nB8 = ((lane >> 4) & 1) * 8;
    const int lsw = (lane & 7) << 4;

    float acc[4][4][4] = {};

    auto load_stage = [&](int t, int buf) {
        const int k0 = t * KC;
        uint32_t sb = sbase + buf * STAGE;
        #pragma unroll
        for (int a = 0; a < NTA; a++) {
            uint32_t tb = sb + a * ATB;
            #pragma unroll
            for (int pp = 0; pp < OPS; pp++) {
                int id = tid + pp * 256;
                if (!TA) {
                    int row = id / CPR, ch = id % CPR;
                    CP_ASYNC16(tb + row * NAT_RB + ch * 16,
                               gpA[a] + (size_t)row * L + k0 + ch * 8);
                } else {
                    int kr = id >> 4, ch = id & 15;
                    CP_ASYNC16(tb + kr * 256 + ((ch ^ (kr & 7)) << 4),
                               gpA[a] + (size_t)(k0 + kr) * L + ch * 8);
                }
            }
        }
        sb += NTA * ATB;
        #pragma unroll
        for (int a = 0; a < NTB; a++) {
            uint32_t tb = sb + a * BTB;
            #pragma unroll
            for (int pp = 0; pp < OPS; pp++) {
                int id = tid + pp * 256;
                if (!TB) {
                    int row = id / CPR, ch = id % CPR;
                    CP_ASYNC16(tb + row * NAT_RB + ch * 16,
                               gpB[a] + (size_t)row * L + k0 + ch * 8);
                } else {
                    int kr = id >> 4, ch = id & 15;
                    CP_ASYNC16(tb + kr * 256 + ((ch ^ (kr & 7)) << 4),
                               gpB[a] + (size_t)(k0 + kr) * L + ch * 8);
                }
            }
        }
    };

    load_stage(0, 0);
    CP_COMMIT();

    for (int t = 0; t < ktiles; t++) {
        CP_WAIT0();          // stage t resident
        __syncthreads();     // stage t visible AND all warps done with buf (t+1)&1
        if (t + 1 < ktiles) { load_stage(t + 1, (t + 1) & 1); CP_COMMIT(); }

        const uint32_t sb = sbase + (t & 1) * STAGE;
        const uint32_t sbB = sb + NTA * ATB;
        #pragma unroll
        for (int ks = 0; ks < KSN; ks++) {
            uint32_t Bf[NTB][8];
            #pragma unroll
            for (int tm = 0; tm < NTB; tm++)
                #pragma unroll
                for (int g2 = 0; g2 < 2; g2++) {
                    if (!TB) {
                        uint32_t a = sbB + tm * BTB + (rowB + g2 * 16) * NAT_RB
                                   + chB * 16 + ks * 32;
                        LDSM4(Bf[tm][g2 * 4 + 0], Bf[tm][g2 * 4 + 1],
                              Bf[tm][g2 * 4 + 2], Bf[tm][g2 * 4 + 3], a);
                    } else {
                        int n_off = warp_n + g2 * 16 + nB8;
                        int kr = ks * 16 + kBrow;
                        uint32_t a = sbB + tm * BTB + kr * 256
                                   + (((n_off >> 3) << 4) ^ lsw);
                        LDSM4T(Bf[tm][g2 * 4 + 0], Bf[tm][g2 * 4 + 1],
                               Bf[tm][g2 * 4 + 2], Bf[tm][g2 * 4 + 3], a);
                    }
                }
            uint32_t Af[16];
            #pragma unroll
            for (int p = 0; p < NP; p++) {
                const int pa = (NP == 3) ? PA3[p] : 0;
                const int pb = (NP == 3) ? PB3[p] : 0;
                const int pap = (p == 0) ? -1 : ((NP == 3) ? PA3[p - 1] : 0);
                if (pa != pap) {
                    #pragma unroll
                    for (int f = 0; f < 4; f++) {
                        if (!TA) {
                            uint32_t a = sb + pa * ATB + (rowA + f * 16) * NAT_RB
                                       + chA * 16 + ks * 32;
                            LDSM4(Af[f * 4 + 0], Af[f * 4 + 1],
                                  Af[f * 4 + 2], Af[f * 4 + 3], a);
                        } else {
                            int m_off = warp_m + f * 16 + mA8;
                            int kr = ks * 16 + kArow;
                            uint32_t a = sb + pa * ATB + kr * 256
                                       + (((m_off >> 3) << 4) ^ lsw);
                            LDSM4T(Af[f * 4 + 0], Af[f * 4 + 1],
                                   Af[f * 4 + 2], Af[f * 4 + 3], a);
                        }
                    }
                }
                #pragma unroll
                for (int f = 0; f < 4; f++)
                    #pragma unroll
                    for (int g = 0; g < 4; g++) {
                        uint32_t b0 = Bf[pb][(g >> 1) * 4 + (g & 1) * 2];
                        uint32_t b1 = Bf[pb][(g >> 1) * 4 + (g & 1) * 2 + 1];
                        mma16816(acc[f][g][0], acc[f][g][1], acc[f][g][2], acc[f][g][3],
                                 Af[f * 4], Af[f * 4 + 1], Af[f * 4 + 2], Af[f * 4 + 3],
                                 b0, b1);
                    }
            }
        }
    }

    float* Ob = ((DUALB && which) ? OutB : Out) + boff;
    #pragma unroll
    for (int f = 0; f < 4; f++)
        #pragma unroll
        for (int g = 0; g < 4; g++) {
            int row = m0 + warp_m + f * 16 + (lane >> 2);
            int col = n0 + warp_n + g * 8 + (lane & 3) * 2;
            *(float2*)(Ob + (size_t)row * L + col) = make_float2(acc[f][g][0], acc[f][g][1]);
            *(float2*)(Ob + (size_t)(row + 8) * L + col) = make_float2(acc[f][g][2], acc[f][g][3]);
            if (EPI16) {
                __half* Oh = Out16 + boff;
                *(__half2*)(Oh + (size_t)row * L + col) =
                    __floats2half2_rn(acc[f][g][0], acc[f][g][1]);
                *(__half2*)(Oh + (size_t)(row + 8) * L + col) =
                    __floats2half2_rn(acc[f][g][2], acc[f][g][3]);
            }
        }
}

// ---------------------------------------------------------------------------
extern "C" void kernel_launch(void* const* d_in, const int* in_sizes, int n_in,
                              void* d_out, int out_size) {
    const float* q = (const float*)d_in[0];
    const float* dmat = (const float*)d_in[1];
    const int* qlen = (const int*)d_in[2];
    const int* dlen = (const int*)d_in[3];

    float* out = (float*)d_out;
    const size_t ten = (size_t)BATCH * L * HD;
    float* out_cd = out;
    float* out_sq = out + ten;
    float* out_sd = out + 2 * ten;

    void *pA, *pq0, *pq1, *pd0, *pd1, *ps, *pwr, *pwc;
    cudaGetSymbolAddress(&pA, g_A);
    cudaGetSymbolAddress(&pq0, g_q0); cudaGetSymbolAddress(&pq1, g_q1);
    cudaGetSymbolAddress(&pd0, g_d0); cudaGetSymbolAddress(&pd1, g_d1);
    cudaGetSymbolAddress(&ps, g_s);
    cudaGetSymbolAddress(&pwr, g_wr); cudaGetSymbolAddress(&pwc, g_wc);

    // K1: Kc=32, 4 natural tiles of 128*80B -> stage 40960, x2 = 81920
    const int SMEM_K1 = 2 * 4 * (128 * 80);
    // K3: Kc=64, natural(wr) 18432 + trans(d) 16384 -> x2 = 69632
    const int SMEM_K3 = 2 * (128 * 144 + 64 * 256);
    // K4/5: Kc=64, 2 trans tiles -> x2 = 65536
    const int SMEM_K45 = 2 * 2 * (64 * 256);
    cudaFuncSetAttribute(k_mma<2, 2, 3, 0, 0, 0, 32, 1, 0>,
                         cudaFuncAttributeMaxDynamicSharedMemorySize, SMEM_K1);
    cudaFuncSetAttribute(k_mma<1, 1, 1, 0, 1, 1, 64, 0, 0>,
                         cudaFuncAttributeMaxDynamicSharedMemorySize, SMEM_K3);
    cudaFuncSetAttribute(k_mma<1, 1, 1, 1, 1, 0, 64, 0, 1>,
                         cudaFuncAttributeMaxDynamicSharedMemorySize, SMEM_K45);

    dim3 gg(HD / 128, L / 128, BATCH);
    int nsplit = (int)(NEL / 4 / 256);

    // 1) 2-way fp16 splits of q AND d in one launch
    k_split2h_dual<<<dim3(nsplit, 2), 256>>>(
        (const float4*)q, (uint2*)pq0, (uint2*)pq1,
        (const float4*)dmat, (uint2*)pd0, (uint2*)pd1);

    // 2) K1: A = q @ d^T  (3 fp16 product terms; skip unconsumed masked tiles)
    k_mma<2, 2, 3, 0, 0, 0, 32, 1, 0><<<gg, 256, SMEM_K1>>>(
        (const __half*)pq0, (const __half*)pq1,
        (const __half*)pd0, (const __half*)pd1,
        nullptr, L, (float*)pA, nullptr, qlen, dlen, nullptr);

    // 3) fused row+col softmax stats in one launch
    k_stats<<<dim3(L / 8, 2, BATCH), 256>>>(qlen, dlen);

    // 4) fused streaming weights (wr + wc, 8 elems/thread, predicated I/O)
    k_weights<<<dim3(L / 2, BATCH), 256>>>(qlen, dlen);

    // 5) K3: sq^T = Wr @ d^T  (A natural, B=d trans; epilogue also emits fp16 sq^T)
    k_mma<1, 1, 1, 0, 1, 1, 64, 0, 0><<<gg, 256, SMEM_K3>>>(
        (const __half*)pwr, nullptr, (const __half*)pd0, nullptr,
        dlen, 0, out_sq, (__half*)ps, nullptr, nullptr, nullptr);

    // 6) K4+K5 in ONE launch: A=wc trans, klen=qlen for both;
    //    blockIdx.x<8 -> B=q^T -> sd^T;  blockIdx.x>=8 -> B=sq^T -> cd^T
    k_mma<1, 1, 1, 1, 1, 0, 64, 0, 1><<<dim3(16, 8, 32), 256, SMEM_K45>>>(
        (const __half*)pwc, nullptr, (const __half*)pq0, (const __half*)ps,
        qlen, 0, out_sd, nullptr, nullptr, nullptr, out_cd);
}